// round 4
// baseline (speedup 1.0000x reference)
#include <cuda_runtime.h>
#include <cstdint>

// Problem constants (fixed by the dataset)
#define MAXN   50048
#define DIN    256
#define DH     256
#define DOUT   64

// Scratch (static device globals — no allocation allowed).
__device__ float g_bufA[MAXN * DH];   // GEMM output h
__device__ float g_bufB[MAXN * DH];   // aggregation output / next-layer input
__device__ float g_dis[MAXN];         // deg -> deg_inv_sqrt

// ---------------------------------------------------------------------------
// Degree / normalization  (edge indices are int32: harness converts int64)
// ---------------------------------------------------------------------------
__global__ void k_deg_init(int n) {
    int i = blockIdx.x * blockDim.x + threadIdx.x;
    if (i < n) g_dis[i] = 1.0f;   // self loop
}

__global__ void k_deg_count(const int* __restrict__ dst, int E, int n) {
    int e = blockIdx.x * blockDim.x + threadIdx.x;
    if (e < E) {
        unsigned d = (unsigned)dst[e];
        if (d < (unsigned)n) atomicAdd(&g_dis[d], 1.0f);
    }
}

__global__ void k_deg_rsqrt(int n) {
    int i = blockIdx.x * blockDim.x + threadIdx.x;
    if (i < n) g_dis[i] = rsqrtf(g_dis[i]);   // deg >= 1 always (self loop)
}

// ---------------------------------------------------------------------------
// GEMM: g_bufA[M,Nc] = A[M,K] @ B[K,Nc]   (fp32, 128x64 tile, 8x4 per thread)
// A = external pointer (layer 1 input x) if useExt, else g_bufB.
// ---------------------------------------------------------------------------
#define BM 128
#define BN 64
#define BK 16
#define TM 8
#define TN 4

__global__ __launch_bounds__(256) void k_gemm(
    const float* __restrict__ A_ext, int useExt,
    const float* __restrict__ B, int M, int K, int Nc)
{
    const float* __restrict__ A = useExt ? A_ext : (const float*)g_bufB;
    float* __restrict__ C = g_bufA;

    __shared__ float As[BK][BM + 1];
    __shared__ float Bs[BK][BN];

    const int tid = threadIdx.x;
    const int tx = tid % 16;         // 16 cols of threads
    const int ty = tid / 16;         // 16 rows of threads
    const int rowBase = blockIdx.y * BM;
    const int colBase = blockIdx.x * BN;

    float acc[TM][TN];
    #pragma unroll
    for (int i = 0; i < TM; i++)
        #pragma unroll
        for (int j = 0; j < TN; j++) acc[i][j] = 0.0f;

    for (int kb = 0; kb < K; kb += BK) {
        // Load A tile: BM x BK (2048 elems, 8 per thread), stored transposed
        #pragma unroll
        for (int i = 0; i < (BM * BK) / 256; i++) {
            int idx = tid + i * 256;
            int k = idx % BK;
            int m = idx / BK;
            int row = rowBase + m;
            As[k][m] = (row < M) ? A[(long long)row * K + kb + k] : 0.0f;
        }
        // Load B tile: BK x BN (1024 elems, 4 per thread), coalesced rows
        #pragma unroll
        for (int i = 0; i < (BK * BN) / 256; i++) {
            int idx = tid + i * 256;
            int n = idx % BN;
            int k = idx / BN;
            Bs[k][n] = B[(long long)(kb + k) * Nc + colBase + n];
        }
        __syncthreads();

        #pragma unroll
        for (int kk = 0; kk < BK; kk++) {
            float a[TM], b[TN];
            #pragma unroll
            for (int i = 0; i < TM; i++) a[i] = As[kk][ty * TM + i];
            #pragma unroll
            for (int j = 0; j < TN; j++) b[j] = Bs[kk][tx * TN + j];
            #pragma unroll
            for (int i = 0; i < TM; i++)
                #pragma unroll
                for (int j = 0; j < TN; j++) acc[i][j] += a[i] * b[j];
        }
        __syncthreads();
    }

    #pragma unroll
    for (int i = 0; i < TM; i++) {
        int row = rowBase + ty * TM + i;
        if (row < M) {
            #pragma unroll
            for (int j = 0; j < TN; j++)
                C[(long long)row * Nc + colBase + tx * TN + j] = acc[i][j];
        }
    }
}

// ---------------------------------------------------------------------------
// Self-loop init: agg[i,f] = g_bufA[i,f] * dis[i]^2  (replaces a memset pass)
// agg = dst_ext if useExt (layer 3 -> d_out), else g_bufB.
// ---------------------------------------------------------------------------
__global__ void k_self_init(float4* __restrict__ dst_ext, int useExt,
                            int total4, int Fq)
{
    float4* __restrict__ agg = useExt ? dst_ext : (float4*)g_bufB;
    const float4* __restrict__ h = (const float4*)g_bufA;
    int idx = blockIdx.x * blockDim.x + threadIdx.x;
    if (idx >= total4) return;
    int i = idx / Fq;
    float d = g_dis[i];
    float s = d * d;
    float4 v = h[idx];
    v.x *= s; v.y *= s; v.z *= s; v.w *= s;
    agg[idx] = v;
}

// ---------------------------------------------------------------------------
// Edge scatter: agg[dst] += g_bufA[src] * dis[src]*dis[dst]
// F/4 threads per edge, float4 gather + 4 atomics each
// ---------------------------------------------------------------------------
template <int F>
__global__ void k_scatter_edges(float* __restrict__ dst_ext, int useExt,
                                const int* __restrict__ src,
                                const int* __restrict__ dst, int E, int n)
{
    float* __restrict__ agg = useExt ? dst_ext : (float*)g_bufB;
    const float4* __restrict__ h = (const float4*)g_bufA;
    const int TPE = F / 4;               // threads per edge
    const int EPB = 256 / TPE;           // edges per block
    int e = blockIdx.x * EPB + threadIdx.x / TPE;
    if (e >= E) return;
    int lane = threadIdx.x % TPE;
    unsigned s = (unsigned)src[e];
    unsigned d = (unsigned)dst[e];
    if (s >= (unsigned)n || d >= (unsigned)n) return;
    float norm = g_dis[s] * g_dis[d];
    float4 v = h[(long long)s * TPE + lane];
    float* out = agg + (long long)d * F + lane * 4;
    atomicAdd(out + 0, v.x * norm);
    atomicAdd(out + 1, v.y * norm);
    atomicAdd(out + 2, v.z * norm);
    atomicAdd(out + 3, v.w * norm);
}

// ---------------------------------------------------------------------------
// Bias (+ optional relu), in place on g_bufB or dst_ext
// ---------------------------------------------------------------------------
__global__ void k_bias_act(float* __restrict__ dst_ext, int useExt,
                           const float* __restrict__ b,
                           int total, int F, int do_relu)
{
    float* __restrict__ x = useExt ? dst_ext : (float*)g_bufB;
    int idx = blockIdx.x * blockDim.x + threadIdx.x;
    if (idx >= total) return;
    float v = x[idx] + b[idx % F];
    if (do_relu) v = fmaxf(v, 0.0f);
    x[idx] = v;
}

// ---------------------------------------------------------------------------
// Launch
// ---------------------------------------------------------------------------
extern "C" void kernel_launch(void* const* d_in, const int* in_sizes, int n_in,
                              void* d_out, int out_size)
{
    const float* x   = (const float*)d_in[0];
    const int*   ei  = (const int*)d_in[1];    // int32 (harness converts int64)
    const float* W1  = (const float*)d_in[2];
    const float* b1  = (const float*)d_in[3];
    const float* W2  = (const float*)d_in[4];
    const float* b2  = (const float*)d_in[5];
    const float* W3  = (const float*)d_in[6];
    const float* b3  = (const float*)d_in[7];
    float*       out = (float*)d_out;

    const int N = in_sizes[0] / DIN;
    const int E = in_sizes[1] / 2;
    const int* srcp = ei;          // row 0 of (2, E)
    const int* dstp = ei + E;      // row 1 of (2, E)

    // --- degrees / normalization ---
    k_deg_init<<<(N + 255) / 256, 256>>>(N);
    k_deg_count<<<(E + 255) / 256, 256>>>(dstp, E, N);
    k_deg_rsqrt<<<(N + 255) / 256, 256>>>(N);

    // ===== Layer 1: h = relu(Agg(x @ W1) + b1)  [result in bufB] =====
    {
        dim3 grid(DH / BN, (N + BM - 1) / BM);
        k_gemm<<<grid, 256>>>(x, 1, W1, N, DIN, DH);
        int total4 = N * DH / 4;
        k_self_init<<<(total4 + 255) / 256, 256>>>(nullptr, 0, total4, DH / 4);
        int epb = 256 / (DH / 4);
        k_scatter_edges<DH><<<(E + epb - 1) / epb, 256>>>(nullptr, 0, srcp, dstp, E, N);
        int total = N * DH;
        k_bias_act<<<(total + 255) / 256, 256>>>(nullptr, 0, b1, total, DH, 1);
    }

    // ===== Layer 2: h = relu(Agg(h @ W2) + b2)  [bufB -> bufA -> bufB] =====
    {
        dim3 grid(DH / BN, (N + BM - 1) / BM);
        k_gemm<<<grid, 256>>>(nullptr, 0, W2, N, DH, DH);
        int total4 = N * DH / 4;
        k_self_init<<<(total4 + 255) / 256, 256>>>(nullptr, 0, total4, DH / 4);
        int epb = 256 / (DH / 4);
        k_scatter_edges<DH><<<(E + epb - 1) / epb, 256>>>(nullptr, 0, srcp, dstp, E, N);
        int total = N * DH;
        k_bias_act<<<(total + 255) / 256, 256>>>(nullptr, 0, b2, total, DH, 1);
    }

    // ===== Layer 3: out = Agg(h @ W3) + b3  [bufB -> bufA -> d_out] =====
    {
        dim3 grid(DOUT / BN, (N + BM - 1) / BM);
        k_gemm<<<grid, 256>>>(nullptr, 0, W3, N, DH, DOUT);
        int total4 = N * DOUT / 4;
        k_self_init<<<(total4 + 255) / 256, 256>>>((float4*)out, 1, total4, DOUT / 4);
        int epb = 256 / (DOUT / 4);
        k_scatter_edges<DOUT><<<(E + epb - 1) / epb, 256>>>(out, 1, srcp, dstp, E, N);
        int total = N * DOUT;
        k_bias_act<<<(total + 255) / 256, 256>>>(out, 1, b3, total, DOUT, 0);
    }
}

// round 5
// speedup vs baseline: 2.5939x; 2.5939x over previous
#include <cuda_runtime.h>
#include <cstdint>

// Problem constants (fixed by the dataset)
#define MAXN   50048
#define MAXE   800000
#define DIN    256
#define DH     256
#define DOUT   64
#define SCAN_B 1024

// Scratch (static device globals — no allocation allowed).
__device__ float g_bufA[MAXN * DH];     // GEMM output, pre-scaled by dis[row]
__device__ float g_bufB[MAXN * DH];     // aggregation output / next-layer input
__device__ float g_dis[MAXN];           // deg^{-1/2}
__device__ int   g_cnt[MAXN];           // degree count, then reused as fill cursor
__device__ int   g_rowp[MAXN + 1];      // CSR row pointer
__device__ int   g_blk[128];            // block sums for scan
__device__ int   g_csrc[MAXE];          // CSR src indices

// ---------------------------------------------------------------------------
// CSR build + normalization
// ---------------------------------------------------------------------------
__global__ void k_zero_cnt(int n) {
    int i = blockIdx.x * blockDim.x + threadIdx.x;
    if (i < n) g_cnt[i] = 0;
}

__global__ void k_count(const int* __restrict__ dst, int E, int n) {
    int e = blockIdx.x * blockDim.x + threadIdx.x;
    if (e < E) {
        unsigned d = (unsigned)dst[e];
        if (d < (unsigned)n) atomicAdd(&g_cnt[d], 1);
    }
}

__global__ void k_dis(int n) {
    int i = blockIdx.x * blockDim.x + threadIdx.x;
    if (i < n) g_dis[i] = rsqrtf((float)(g_cnt[i] + 1));   // +1 self loop
}

// Inclusive scan within blocks of SCAN_B; block totals to g_blk.
__global__ void k_scan1(int n) {
    __shared__ int sh[SCAN_B];
    int i = blockIdx.x * SCAN_B + threadIdx.x;
    int v = (i < n) ? g_cnt[i] : 0;
    sh[threadIdx.x] = v;
    __syncthreads();
    #pragma unroll
    for (int off = 1; off < SCAN_B; off <<= 1) {
        int t = (threadIdx.x >= off) ? sh[threadIdx.x - off] : 0;
        __syncthreads();
        sh[threadIdx.x] += t;
        __syncthreads();
    }
    if (i < n) g_rowp[i + 1] = sh[threadIdx.x];       // inclusive within block
    if (threadIdx.x == SCAN_B - 1) g_blk[blockIdx.x] = sh[SCAN_B - 1];
}

// Exclusive scan of block sums (single block, nb <= 128).
__global__ void k_scan2(int nb) {
    __shared__ int sh[128];
    int v = (threadIdx.x < nb) ? g_blk[threadIdx.x] : 0;
    sh[threadIdx.x] = v;
    __syncthreads();
    #pragma unroll
    for (int off = 1; off < 128; off <<= 1) {
        int t = (threadIdx.x >= off) ? sh[threadIdx.x - off] : 0;
        __syncthreads();
        sh[threadIdx.x] += t;
        __syncthreads();
    }
    if (threadIdx.x < nb)
        g_blk[threadIdx.x] = (threadIdx.x > 0) ? sh[threadIdx.x - 1] : 0;
}

// Add block offsets; reset cursors; set rowp[0].
__global__ void k_scan3(int n) {
    int i = blockIdx.x * blockDim.x + threadIdx.x;
    if (i < n) {
        g_rowp[i + 1] += g_blk[i / SCAN_B];
        g_cnt[i] = 0;
    }
    if (i == 0) g_rowp[0] = 0;
}

__global__ void k_fill(const int* __restrict__ src, const int* __restrict__ dst,
                       int E, int n) {
    int e = blockIdx.x * blockDim.x + threadIdx.x;
    if (e >= E) return;
    unsigned s = (unsigned)src[e];
    unsigned d = (unsigned)dst[e];
    if (s >= (unsigned)n || d >= (unsigned)n) return;
    int pos = g_rowp[d] + atomicAdd(&g_cnt[d], 1);
    if (pos < MAXE) g_csrc[pos] = (int)s;
}

// ---------------------------------------------------------------------------
// GEMM: g_bufA[M,Nc] = (A[M,K] @ B[K,Nc]) * dis[row]   (fp32, 128x64 tile)
// A = external pointer (layer 1 input x) if useExt, else g_bufB.
// ---------------------------------------------------------------------------
#define BM 128
#define BN 64
#define BK 16
#define TM 8
#define TN 4

__global__ __launch_bounds__(256) void k_gemm(
    const float* __restrict__ A_ext, int useExt,
    const float* __restrict__ B, int M, int K, int Nc)
{
    const float* __restrict__ A = useExt ? A_ext : (const float*)g_bufB;
    float* __restrict__ C = g_bufA;

    __shared__ float As[BK][BM + 1];
    __shared__ float Bs[BK][BN];

    const int tid = threadIdx.x;
    const int tx = tid % 16;
    const int ty = tid / 16;
    const int rowBase = blockIdx.y * BM;
    const int colBase = blockIdx.x * BN;

    float acc[TM][TN];
    #pragma unroll
    for (int i = 0; i < TM; i++)
        #pragma unroll
        for (int j = 0; j < TN; j++) acc[i][j] = 0.0f;

    for (int kb = 0; kb < K; kb += BK) {
        #pragma unroll
        for (int i = 0; i < (BM * BK) / 256; i++) {
            int idx = tid + i * 256;
            int k = idx % BK;
            int m = idx / BK;
            int row = rowBase + m;
            As[k][m] = (row < M) ? A[(long long)row * K + kb + k] : 0.0f;
        }
        #pragma unroll
        for (int i = 0; i < (BK * BN) / 256; i++) {
            int idx = tid + i * 256;
            int n = idx % BN;
            int k = idx / BN;
            Bs[k][n] = B[(long long)(kb + k) * Nc + colBase + n];
        }
        __syncthreads();

        #pragma unroll
        for (int kk = 0; kk < BK; kk++) {
            float a[TM], b[TN];
            #pragma unroll
            for (int i = 0; i < TM; i++) a[i] = As[kk][ty * TM + i];
            #pragma unroll
            for (int j = 0; j < TN; j++) b[j] = Bs[kk][tx * TN + j];
            #pragma unroll
            for (int i = 0; i < TM; i++)
                #pragma unroll
                for (int j = 0; j < TN; j++) acc[i][j] += a[i] * b[j];
        }
        __syncthreads();
    }

    #pragma unroll
    for (int i = 0; i < TM; i++) {
        int row = rowBase + ty * TM + i;
        if (row < M) {
            float dd = g_dis[row];
            #pragma unroll
            for (int j = 0; j < TN; j++)
                C[(long long)row * Nc + colBase + tx * TN + j] = acc[i][j] * dd;
        }
    }
}

// ---------------------------------------------------------------------------
// CSR gather aggregation (fused self-loop + bias + relu):
//   out[i] = dis[i] * ( hs[i] + sum_{s in CSR[i]} hs[s] ) + b ;  hs = dis*h
// F/4 lanes per node, float4 per thread.
// ---------------------------------------------------------------------------
template <int F>
__global__ __launch_bounds__(256) void k_gather(
    float4* __restrict__ dst_ext, int useExt,
    const float* __restrict__ bias, int do_relu, int n)
{
    const int L = F / 4;                              // lanes per node
    float4* __restrict__ out = useExt ? dst_ext : (float4*)g_bufB;
    const float4* __restrict__ hs = (const float4*)g_bufA;

    int node = blockIdx.x * (256 / L) + threadIdx.x / L;
    if (node >= n) return;
    int lane = threadIdx.x % L;

    float4 acc = hs[(long long)node * L + lane];      // self term (dis[i]*h[i])
    int p0 = g_rowp[node], p1 = g_rowp[node + 1];
    for (int p = p0; p < p1; p++) {
        int s = g_csrc[p];
        float4 v = hs[(long long)s * L + lane];
        acc.x += v.x; acc.y += v.y; acc.z += v.z; acc.w += v.w;
    }
    float dd = g_dis[node];
    float4 b4 = ((const float4*)bias)[lane];
    float4 o;
    o.x = acc.x * dd + b4.x;
    o.y = acc.y * dd + b4.y;
    o.z = acc.z * dd + b4.z;
    o.w = acc.w * dd + b4.w;
    if (do_relu) {
        o.x = fmaxf(o.x, 0.0f); o.y = fmaxf(o.y, 0.0f);
        o.z = fmaxf(o.z, 0.0f); o.w = fmaxf(o.w, 0.0f);
    }
    out[(long long)node * L + lane] = o;
}

// ---------------------------------------------------------------------------
// Launch
// ---------------------------------------------------------------------------
extern "C" void kernel_launch(void* const* d_in, const int* in_sizes, int n_in,
                              void* d_out, int out_size)
{
    const float* x   = (const float*)d_in[0];
    const int*   ei  = (const int*)d_in[1];    // int32 (harness converts int64)
    const float* W1  = (const float*)d_in[2];
    const float* b1  = (const float*)d_in[3];
    const float* W2  = (const float*)d_in[4];
    const float* b2  = (const float*)d_in[5];
    const float* W3  = (const float*)d_in[6];
    const float* b3  = (const float*)d_in[7];
    float*       out = (float*)d_out;

    const int N = in_sizes[0] / DIN;
    const int E = in_sizes[1] / 2;
    const int* srcp = ei;          // row 0 of (2, E)
    const int* dstp = ei + E;      // row 1 of (2, E)

    // --- CSR build + normalization ---
    k_zero_cnt<<<(N + 255) / 256, 256>>>(N);
    k_count<<<(E + 255) / 256, 256>>>(dstp, E, N);
    k_dis<<<(N + 255) / 256, 256>>>(N);
    int nb = (N + SCAN_B - 1) / SCAN_B;
    k_scan1<<<nb, SCAN_B>>>(N);
    k_scan2<<<1, 128>>>(nb);
    k_scan3<<<(N + 255) / 256, 256>>>(N);
    k_fill<<<(E + 255) / 256, 256>>>(srcp, dstp, E, N);

    // ===== Layer 1: bufB = relu(Agg(x @ W1) + b1) =====
    {
        dim3 grid(DH / BN, (N + BM - 1) / BM);
        k_gemm<<<grid, 256>>>(x, 1, W1, N, DIN, DH);
        int blocks = (N + (256 / (DH / 4)) - 1) / (256 / (DH / 4));
        k_gather<DH><<<blocks, 256>>>(nullptr, 0, b1, 1, N);
    }

    // ===== Layer 2: bufB = relu(Agg(bufB @ W2) + b2) =====
    {
        dim3 grid(DH / BN, (N + BM - 1) / BM);
        k_gemm<<<grid, 256>>>(nullptr, 0, W2, N, DH, DH);
        int blocks = (N + (256 / (DH / 4)) - 1) / (256 / (DH / 4));
        k_gather<DH><<<blocks, 256>>>(nullptr, 0, b2, 1, N);
    }

    // ===== Layer 3: out = Agg(bufB @ W3) + b3 =====
    {
        dim3 grid(DOUT / BN, (N + BM - 1) / BM);
        k_gemm<<<grid, 256>>>(nullptr, 0, W3, N, DH, DOUT);
        int blocks = (N + (256 / (DOUT / 4)) - 1) / (256 / (DOUT / 4));
        k_gather<DOUT><<<blocks, 256>>>((float4*)out, 1, b3, 0, N);
    }
}

// round 7
// speedup vs baseline: 5.0395x; 1.9428x over previous
#include <cuda_runtime.h>
#include <cstdint>

// Problem constants (fixed by the dataset)
#define MAXN   50048
#define MAXE   800000
#define DIN    256
#define DH     256
#define DOUT   64
#define SCAN_B 1024

// Scratch (static device globals — no allocation allowed).
__device__ float g_bufA[MAXN * DH];     // GEMM output, pre-scaled by dis[row]
__device__ float g_bufB[MAXN * DH];     // aggregation output / next-layer input
__device__ float g_dis[MAXN];           // deg^{-1/2}
__device__ int   g_cnt[MAXN];           // degree count, then fill cursor
__device__ int   g_rowp[MAXN + 1];      // CSR row pointer
__device__ int   g_blk[128];            // block sums for scan
__device__ int   g_csrc[MAXE];          // CSR src indices

__device__ __forceinline__ float tf32_rna(float x) {
    uint32_t r;
    asm("cvt.rna.tf32.f32 %0, %1;" : "=r"(r) : "f"(x));
    return __uint_as_float(r);
}

#define MMA_TF32(D, Ar, Br) \
    asm volatile("mma.sync.aligned.m16n8k8.row.col.f32.tf32.tf32.f32 " \
        "{%0,%1,%2,%3}, {%4,%5,%6,%7}, {%8,%9}, {%0,%1,%2,%3};" \
        : "+f"((D)[0]), "+f"((D)[1]), "+f"((D)[2]), "+f"((D)[3]) \
        : "r"((Ar)[0]), "r"((Ar)[1]), "r"((Ar)[2]), "r"((Ar)[3]), \
          "r"((Br)[0]), "r"((Br)[1]))

// ===========================================================================
// CSR build + normalization
// ===========================================================================
__global__ void k_zero_cnt(int n) {
    int i = blockIdx.x * blockDim.x + threadIdx.x;
    if (i < n) g_cnt[i] = 0;
}

__global__ void k_count(const int* __restrict__ dst, int E, int n) {
    int e = blockIdx.x * blockDim.x + threadIdx.x;
    if (e < E) {
        unsigned d = (unsigned)dst[e];
        if (d < (unsigned)n) atomicAdd(&g_cnt[d], 1);
    }
}

__global__ void k_dis(int n) {
    int i = blockIdx.x * blockDim.x + threadIdx.x;
    if (i < n) g_dis[i] = rsqrtf((float)(g_cnt[i] + 1));
}

__global__ void k_scan1(int n) {
    __shared__ int sh[SCAN_B];
    int i = blockIdx.x * SCAN_B + threadIdx.x;
    int v = (i < n) ? g_cnt[i] : 0;
    sh[threadIdx.x] = v;
    __syncthreads();
    #pragma unroll
    for (int off = 1; off < SCAN_B; off <<= 1) {
        int t = (threadIdx.x >= off) ? sh[threadIdx.x - off] : 0;
        __syncthreads();
        sh[threadIdx.x] += t;
        __syncthreads();
    }
    if (i < n) g_rowp[i + 1] = sh[threadIdx.x];
    if (threadIdx.x == SCAN_B - 1) g_blk[blockIdx.x] = sh[SCAN_B - 1];
}

__global__ void k_scan2(int nb) {
    __shared__ int sh[128];
    int v = (threadIdx.x < nb) ? g_blk[threadIdx.x] : 0;
    sh[threadIdx.x] = v;
    __syncthreads();
    #pragma unroll
    for (int off = 1; off < 128; off <<= 1) {
        int t = (threadIdx.x >= off) ? sh[threadIdx.x - off] : 0;
        __syncthreads();
        sh[threadIdx.x] += t;
        __syncthreads();
    }
    if (threadIdx.x < nb)
        g_blk[threadIdx.x] = (threadIdx.x > 0) ? sh[threadIdx.x - 1] : 0;
}

__global__ void k_scan3(int n) {
    int i = blockIdx.x * blockDim.x + threadIdx.x;
    if (i < n) {
        g_rowp[i + 1] += g_blk[i / SCAN_B];
        g_cnt[i] = 0;
    }
    if (i == 0) g_rowp[0] = 0;
}

__global__ void k_fill(const int* __restrict__ src, const int* __restrict__ dst,
                       int E, int n) {
    int e = blockIdx.x * blockDim.x + threadIdx.x;
    if (e >= E) return;
    unsigned s = (unsigned)src[e];
    unsigned d = (unsigned)dst[e];
    if (s >= (unsigned)n || d >= (unsigned)n) return;
    int pos = g_rowp[d] + atomicAdd(&g_cnt[d], 1);
    if (pos < MAXE) g_csrc[pos] = (int)s;
}

// ===========================================================================
// tf32 mma.sync GEMM: g_bufA[M,Nc] = (A[M,256] @ W[256,Nc]) * dis[row]
// Block tile 128x64, 8 warps (4x2), warp tile 32x32 (2x4 of m16n8k8), BK=32.
// ===========================================================================
__global__ __launch_bounds__(256) void k_gemm_mma(
    const float* __restrict__ A_ext, int useExt,
    const float* __restrict__ W, int M, int Nc)
{
    const float* __restrict__ A = useExt ? A_ext : (const float*)g_bufB;

    __shared__ float As[128][40];   // [m][k], pad 8 -> frag bank = 8*gid+tig
    __shared__ float Bs[32][72];    // [k][n], pad 8 -> frag bank = 8*tig+gid

    const int tid = threadIdx.x;
    const int lane = tid & 31;
    const int wid = tid >> 5;
    const int wm = wid & 3;          // 0..3 (M dir)
    const int wn = wid >> 2;         // 0..1 (N dir)
    const int gid = lane >> 2;
    const int tig = lane & 3;
    const int rowBase = blockIdx.y * 128;
    const int colBase = blockIdx.x * 64;

    // A-load coords: 4 x float4 per thread, row-major, 8 float4 per 32-float row
    const int la_row = tid >> 3;          // +32 per i
    const int la_c4  = tid & 7;
    // B-load coords: 2 x float4 per thread, 16 float4 per 64-float row
    const int lb_k  = tid >> 4;           // +16 per i
    const int lb_c4 = tid & 15;

    float acc[2][4][4];
    #pragma unroll
    for (int mt = 0; mt < 2; mt++)
        #pragma unroll
        for (int nt = 0; nt < 4; nt++)
            #pragma unroll
            for (int j = 0; j < 4; j++) acc[mt][nt][j] = 0.0f;

    float4 pa[4], pb[2];

    // Prefetch kb = 0
    #pragma unroll
    for (int i = 0; i < 4; i++) {
        int grow = rowBase + la_row + i * 32;
        pa[i] = (grow < M) ? ((const float4*)A)[(long long)grow * 64 + la_c4]
                           : make_float4(0.f, 0.f, 0.f, 0.f);
    }
    #pragma unroll
    for (int i = 0; i < 2; i++) {
        int k = lb_k + i * 16;
        pb[i] = *(const float4*)(W + (long long)k * Nc + colBase + lb_c4 * 4);
    }

    #pragma unroll 1
    for (int kb = 0; kb < 8; kb++) {
        // Store prefetched tile to SMEM (tf32-rounded)
        #pragma unroll
        for (int i = 0; i < 4; i++) {
            float4 v = pa[i];
            v.x = tf32_rna(v.x); v.y = tf32_rna(v.y);
            v.z = tf32_rna(v.z); v.w = tf32_rna(v.w);
            *(float4*)&As[la_row + i * 32][la_c4 * 4] = v;
        }
        #pragma unroll
        for (int i = 0; i < 2; i++) {
            float4 v = pb[i];
            v.x = tf32_rna(v.x); v.y = tf32_rna(v.y);
            v.z = tf32_rna(v.z); v.w = tf32_rna(v.w);
            *(float4*)&Bs[lb_k + i * 16][lb_c4 * 4] = v;
        }
        __syncthreads();

        // Prefetch next tile (hidden behind MMA compute)
        if (kb < 7) {
            #pragma unroll
            for (int i = 0; i < 4; i++) {
                int grow = rowBase + la_row + i * 32;
                pa[i] = (grow < M)
                    ? ((const float4*)A)[(long long)grow * 64 + (kb + 1) * 8 + la_c4]
                    : make_float4(0.f, 0.f, 0.f, 0.f);
            }
            #pragma unroll
            for (int i = 0; i < 2; i++) {
                int k = (kb + 1) * 32 + lb_k + i * 16;
                pb[i] = *(const float4*)(W + (long long)k * Nc + colBase + lb_c4 * 4);
            }
        }

        // Compute: 4 k-steps of 8
        #pragma unroll
        for (int ks = 0; ks < 4; ks++) {
            int k0 = ks * 8;
            uint32_t af[2][4], bf[4][2];
            #pragma unroll
            for (int mt = 0; mt < 2; mt++) {
                int m0 = wm * 32 + mt * 16 + gid;
                af[mt][0] = __float_as_uint(As[m0][k0 + tig]);
                af[mt][1] = __float_as_uint(As[m0 + 8][k0 + tig]);
                af[mt][2] = __float_as_uint(As[m0][k0 + tig + 4]);
                af[mt][3] = __float_as_uint(As[m0 + 8][k0 + tig + 4]);
            }
            #pragma unroll
            for (int nt = 0; nt < 4; nt++) {
                int n0 = wn * 32 + nt * 8 + gid;
                bf[nt][0] = __float_as_uint(Bs[k0 + tig][n0]);
                bf[nt][1] = __float_as_uint(Bs[k0 + tig + 4][n0]);
            }
            #pragma unroll
            for (int mt = 0; mt < 2; mt++)
                #pragma unroll
                for (int nt = 0; nt < 4; nt++)
                    MMA_TF32(acc[mt][nt], af[mt], bf[nt]);
        }
        __syncthreads();
    }

    // Epilogue: scale by dis[row], store float2 per fragment half
    #pragma unroll
    for (int mt = 0; mt < 2; mt++) {
        int r0 = rowBase + wm * 32 + mt * 16 + gid;
        int r1 = r0 + 8;
        float s0 = (r0 < M) ? g_dis[r0] : 0.f;
        float s1 = (r1 < M) ? g_dis[r1] : 0.f;
        #pragma unroll
        for (int nt = 0; nt < 4; nt++) {
            int c = colBase + wn * 32 + nt * 8 + tig * 2;
            if (r0 < M) {
                float2 o = make_float2(acc[mt][nt][0] * s0, acc[mt][nt][1] * s0);
                *(float2*)(g_bufA + (long long)r0 * Nc + c) = o;
            }
            if (r1 < M) {
                float2 o = make_float2(acc[mt][nt][2] * s1, acc[mt][nt][3] * s1);
                *(float2*)(g_bufA + (long long)r1 * Nc + c) = o;
            }
        }
    }
}

// ===========================================================================
// CSR gather aggregation (fused self-loop + bias + relu)
// ===========================================================================
template <int F>
__global__ __launch_bounds__(256) void k_gather(
    float4* __restrict__ dst_ext, int useExt,
    const float* __restrict__ bias, int do_relu, int n)
{
    const int L = F / 4;
    float4* __restrict__ out = useExt ? dst_ext : (float4*)g_bufB;
    const float4* __restrict__ hs = (const float4*)g_bufA;

    int node = blockIdx.x * (256 / L) + threadIdx.x / L;
    if (node >= n) return;
    int lane = threadIdx.x % L;

    float4 acc = hs[(long long)node * L + lane];
    int p0 = g_rowp[node], p1 = g_rowp[node + 1];
    for (int p = p0; p < p1; p++) {
        int s = g_csrc[p];
        float4 v = hs[(long long)s * L + lane];
        acc.x += v.x; acc.y += v.y; acc.z += v.z; acc.w += v.w;
    }
    float dd = g_dis[node];
    float4 b4 = ((const float4*)bias)[lane];
    float4 o;
    o.x = acc.x * dd + b4.x;
    o.y = acc.y * dd + b4.y;
    o.z = acc.z * dd + b4.z;
    o.w = acc.w * dd + b4.w;
    if (do_relu) {
        o.x = fmaxf(o.x, 0.0f); o.y = fmaxf(o.y, 0.0f);
        o.z = fmaxf(o.z, 0.0f); o.w = fmaxf(o.w, 0.0f);
    }
    out[(long long)node * L + lane] = o;
}

// ===========================================================================
// Launch
// ===========================================================================
extern "C" void kernel_launch(void* const* d_in, const int* in_sizes, int n_in,
                              void* d_out, int out_size)
{
    const float* x   = (const float*)d_in[0];
    const int*   ei  = (const int*)d_in[1];
    const float* W1  = (const float*)d_in[2];
    const float* b1  = (const float*)d_in[3];
    const float* W2  = (const float*)d_in[4];
    const float* b2  = (const float*)d_in[5];
    const float* W3  = (const float*)d_in[6];
    const float* b3  = (const float*)d_in[7];
    float*       out = (float*)d_out;

    const int N = in_sizes[0] / DIN;
    const int E = in_sizes[1] / 2;
    const int* srcp = ei;
    const int* dstp = ei + E;

    // --- CSR build + normalization ---
    k_zero_cnt<<<(N + 255) / 256, 256>>>(N);
    k_count<<<(E + 255) / 256, 256>>>(dstp, E, N);
    k_dis<<<(N + 255) / 256, 256>>>(N);
    int nb = (N + SCAN_B - 1) / SCAN_B;
    k_scan1<<<nb, SCAN_B>>>(N);
    k_scan2<<<1, 128>>>(nb);
    k_scan3<<<(N + 255) / 256, 256>>>(N);
    k_fill<<<(E + 255) / 256, 256>>>(srcp, dstp, E, N);

    int mtiles = (N + 127) / 128;

    // ===== Layer 1 =====
    {
        dim3 grid(DH / 64, mtiles);
        k_gemm_mma<<<grid, 256>>>(x, 1, W1, N, DH);
        int blocks = (N + (256 / (DH / 4)) - 1) / (256 / (DH / 4));
        k_gather<DH><<<blocks, 256>>>(nullptr, 0, b1, 1, N);
    }
    // ===== Layer 2 =====
    {
        dim3 grid(DH / 64, mtiles);
        k_gemm_mma<<<grid, 256>>>(nullptr, 0, W2, N, DH);
        int blocks = (N + (256 / (DH / 4)) - 1) / (256 / (DH / 4));
        k_gather<DH><<<blocks, 256>>>(nullptr, 0, b2, 1, N);
    }
    // ===== Layer 3 =====
    {
        dim3 grid(DOUT / 64, mtiles);
        k_gemm_mma<<<grid, 256>>>(nullptr, 0, W3, N, DOUT);
        int blocks = (N + (256 / (DOUT / 4)) - 1) / (256 / (DOUT / 4));
        k_gather<DOUT><<<blocks, 256>>>((float4*)out, 1, b3, 0, N);
    }
}